// round 16
// baseline (speedup 1.0000x reference)
#include <cuda_runtime.h>
#include <cuda_fp16.h>
#include <stdint.h>

// Problem constants (this instance):
//   NUM_EMB=200000, DIM=64, UPDATE_COUNT=2, HASHED_SIZE=3,200,000
//   NUM_BAGS=16384, BAG_LEN=50, TOTAL=819200
// Inputs: x(int32), offsets(int32), hashed_weight(f32), weight_idx(int32)
// Output: float32 [NUM_BAGS, DIM]
//
// FINAL — converged at the structural floor. Six runs of this exact
// source: 106.66/106.98/107.23/107.23/107.23/112.74us (env noise ~+-3us).
// Wavefront ledger (within 1% of measurement):
//   K1: 3.2M widx stream + 25.6M random 4B gathers (1 wf each; hits cost
//       wavefronts too) + 0.8M emb stores = 29.6M wf
//   -> 29.6M / 148 SM / 1.88GHz ~= 106us; K2 largely hidden.
// Gather count is algorithmically minimal (4.1x unique-id dedupe already
// applied; indices uniform-random -> no coalescing/sorting/partitioning
// can reduce wavefronts).
// Measured/eliminated: MLP>2 (R6 regress), .cg on K2 (R7 regress),
// PDL (R10 regress), unused-id skip, fp16 hw table (wf invariant),
// LDGSTS/TMA gathers, smem/DSMEM partitioning, fusion, K1 granularity.

#define UPDATE_COUNT 2
#define EMB_CAPACITY (200000 * 64)

// Combined table in fp16: emb[e*64+d] = (half)(hw[widx[0,e,d]] + hw[widx[1,e,d]])
__device__ __half g_emb_h[EMB_CAPACITY];

// ---------------------------------------------------------------------------
// Kernel 1: build combined table. At the L1tex wavefront floor. widx .cs
// (streaming; keep hot hw resident in L2), hw .cg (skip L1).
// ---------------------------------------------------------------------------
__global__ void __launch_bounds__(256) build_emb_kernel(
    const int4* __restrict__ widx,
    const float* __restrict__ hw,
    int n8,                       // emb_elems / 8
    int stride4)                  // emb_elems / 4 (u-stride in int4 units)
{
    int i = blockIdx.x * blockDim.x + threadIdx.x;
    if (i >= n8) return;

    int4 a0 = __ldcs(&widx[2 * i]);
    int4 a1 = __ldcs(&widx[2 * i + 1]);
    int4 b0 = __ldcs(&widx[2 * i + stride4]);
    int4 b1 = __ldcs(&widx[2 * i + 1 + stride4]);

    float f0 = __ldcg(&hw[a0.x]) + __ldcg(&hw[b0.x]);
    float f1 = __ldcg(&hw[a0.y]) + __ldcg(&hw[b0.y]);
    float f2 = __ldcg(&hw[a0.z]) + __ldcg(&hw[b0.z]);
    float f3 = __ldcg(&hw[a0.w]) + __ldcg(&hw[b0.w]);
    float f4 = __ldcg(&hw[a1.x]) + __ldcg(&hw[b1.x]);
    float f5 = __ldcg(&hw[a1.y]) + __ldcg(&hw[b1.y]);
    float f6 = __ldcg(&hw[a1.z]) + __ldcg(&hw[b1.z]);
    float f7 = __ldcg(&hw[a1.w]) + __ldcg(&hw[b1.w]);

    __half2 h0 = __floats2half2_rn(f0, f1);
    __half2 h1 = __floats2half2_rn(f2, f3);
    __half2 h2 = __floats2half2_rn(f4, f5);
    __half2 h3 = __floats2half2_rn(f6, f7);

    uint4 o;
    o.x = *reinterpret_cast<uint32_t*>(&h0);
    o.y = *reinterpret_cast<uint32_t*>(&h1);
    o.z = *reinterpret_cast<uint32_t*>(&h2);
    o.w = *reinterpret_cast<uint32_t*>(&h3);
    reinterpret_cast<uint4*>(g_emb_h)[i] = o;
}

// ---------------------------------------------------------------------------
// Kernel 2: embedding bag. Warp-per-bag; fp16 rows are 128B -> one warp
// LDG.128 covers FOUR token rows (lane groups of 8). 8-token loop = MLP 2
// per lane. HADD2 accumulation (chain ~13, |partial|<0.06, fp16-safe).
// fp32 fold across the 4 token groups + 256B coalesced store.
// ---------------------------------------------------------------------------
__global__ void __launch_bounds__(256) bag_sum_kernel(
    const int* __restrict__ x,
    const int* __restrict__ offsets,
    float* __restrict__ out,
    int num_bags, int total)
{
    const int BPB = 8;                      // bags (warps) per block
    __shared__ int sh[BPB][64];

    int w    = threadIdx.x >> 5;
    int lane = threadIdx.x & 31;
    int bag  = blockIdx.x * BPB + w;
    if (bag >= num_bags) return;

    int start = __ldg(&offsets[bag]);
    int end   = (bag + 1 < num_bags) ? __ldg(&offsets[bag + 1]) : total;
    int len   = end - start;

    for (int t = lane; t < len; t += 32)
        sh[w][t] = __ldg(&x[start + t]);
    __syncwarp();

    const uint4* __restrict__ emb16 = reinterpret_cast<const uint4*>(g_emb_h);
    int g = lane >> 3;                      // token group 0..3
    int q = lane & 7;                       // 16B chunk within 128B row

    __half2 acc0 = __float2half2_rn(0.f);
    __half2 acc1 = acc0, acc2 = acc0, acc3 = acc0;

    int t = 0;
    // 8 tokens per iteration: 2 independent LDG.128 in flight per lane
    for (; t + 8 <= len; t += 8) {
        uint4 va = __ldg(&emb16[(unsigned)sh[w][t + 0 + g] * 8 + q]);
        uint4 vb = __ldg(&emb16[(unsigned)sh[w][t + 4 + g] * 8 + q]);
        acc0 = __hadd2(acc0, *reinterpret_cast<const __half2*>(&va.x));
        acc1 = __hadd2(acc1, *reinterpret_cast<const __half2*>(&va.y));
        acc2 = __hadd2(acc2, *reinterpret_cast<const __half2*>(&va.z));
        acc3 = __hadd2(acc3, *reinterpret_cast<const __half2*>(&va.w));
        acc0 = __hadd2(acc0, *reinterpret_cast<const __half2*>(&vb.x));
        acc1 = __hadd2(acc1, *reinterpret_cast<const __half2*>(&vb.y));
        acc2 = __hadd2(acc2, *reinterpret_cast<const __half2*>(&vb.z));
        acc3 = __hadd2(acc3, *reinterpret_cast<const __half2*>(&vb.w));
    }
    for (; t + 4 <= len; t += 4) {
        uint4 v = __ldg(&emb16[(unsigned)sh[w][t + g] * 8 + q]);
        acc0 = __hadd2(acc0, *reinterpret_cast<const __half2*>(&v.x));
        acc1 = __hadd2(acc1, *reinterpret_cast<const __half2*>(&v.y));
        acc2 = __hadd2(acc2, *reinterpret_cast<const __half2*>(&v.z));
        acc3 = __hadd2(acc3, *reinterpret_cast<const __half2*>(&v.w));
    }
    if (t + g < len) {                      // tail: 1-3 tokens
        uint4 v = __ldg(&emb16[(unsigned)sh[w][t + g] * 8 + q]);
        acc0 = __hadd2(acc0, *reinterpret_cast<const __half2*>(&v.x));
        acc1 = __hadd2(acc1, *reinterpret_cast<const __half2*>(&v.y));
        acc2 = __hadd2(acc2, *reinterpret_cast<const __half2*>(&v.z));
        acc3 = __hadd2(acc3, *reinterpret_cast<const __half2*>(&v.w));
    }

    // Convert to fp32, then fold the 4 token groups
    float2 a0 = __half22float2(acc0);
    float2 a1 = __half22float2(acc1);
    float2 a2 = __half22float2(acc2);
    float2 a3 = __half22float2(acc3);

    #pragma unroll
    for (int off = 16; off >= 8; off >>= 1) {
        a0.x += __shfl_xor_sync(0xffffffffu, a0.x, off);
        a0.y += __shfl_xor_sync(0xffffffffu, a0.y, off);
        a1.x += __shfl_xor_sync(0xffffffffu, a1.x, off);
        a1.y += __shfl_xor_sync(0xffffffffu, a1.y, off);
        a2.x += __shfl_xor_sync(0xffffffffu, a2.x, off);
        a2.y += __shfl_xor_sync(0xffffffffu, a2.y, off);
        a3.x += __shfl_xor_sync(0xffffffffu, a3.x, off);
        a3.y += __shfl_xor_sync(0xffffffffu, a3.y, off);
    }

    if (lane < 8) {                         // 8 lanes x 32B = 256B coalesced
        float4 lo = make_float4(a0.x, a0.y, a1.x, a1.y);
        float4 hi = make_float4(a2.x, a2.y, a3.x, a3.y);
        float4* o = reinterpret_cast<float4*>(out) + (unsigned)bag * 16 + q * 2;
        o[0] = lo;
        o[1] = hi;
    }
}

// ---------------------------------------------------------------------------
extern "C" void kernel_launch(void* const* d_in, const int* in_sizes, int n_in,
                              void* d_out, int out_size)
{
    const int*   x       = (const int*)  d_in[0];
    const int*   offsets = (const int*)  d_in[1];
    const float* hw      = (const float*)d_in[2];
    const int*   widx    = (const int*)  d_in[3];

    int total     = in_sizes[0];
    int num_bags  = in_sizes[1];
    int wid_sz    = in_sizes[3];
    int emb_elems = wid_sz / UPDATE_COUNT;

    int n8 = emb_elems / 8;
    int threads1 = 256;
    int blocks1  = (n8 + threads1 - 1) / threads1;
    build_emb_kernel<<<blocks1, threads1>>>(
        (const int4*)widx, hw, n8, emb_elems / 4);

    int blocks2 = (num_bags + 7) / 8;
    bag_sum_kernel<<<blocks2, 256>>>(x, offsets, (float*)d_out, num_bags, total);
}

// round 17
// speedup vs baseline: 1.0021x; 1.0021x over previous
#include <cuda_runtime.h>
#include <cuda_fp16.h>
#include <stdint.h>

// Problem constants (this instance):
//   NUM_EMB=200000, DIM=64, UPDATE_COUNT=2, HASHED_SIZE=3,200,000
//   NUM_BAGS=16384, BAG_LEN=50, TOTAL=819200
// Inputs: x(int32), offsets(int32), hashed_weight(f32), weight_idx(int32)
// Output: float32 [NUM_BAGS, DIM]
//
// FINAL — converged at the structural floor. Seven runs of this exact
// source: 106.66/106.98/107.23x3/107.26/112.74us (true time 107.1+-0.2us,
// env outliers aside).
// Wavefront ledger (within 1% of measurement):
//   K1: 3.2M widx stream + 25.6M random 4B gathers (1 wf each; hits cost
//       wavefronts too) + 0.8M emb stores = 29.6M wf
//   -> 29.6M / 148 SM / 1.88GHz ~= 106us; K2 largely hidden.
// Gather count is algorithmically minimal (4.1x unique-id dedupe applied;
// indices uniform-random -> no coalescing/sorting/partitioning reduces it;
// unused-id skip nets -1.3us; K1/K2 overlap blocked by full dependency).
// Measured/eliminated: MLP>2 (R6 regress), .cg on K2 (R7 regress),
// PDL (R10 regress), fp16 hw table (wf invariant), LDGSTS/TMA gathers,
// smem/DSMEM partitioning, fusion, K1 granularity (issue not binding).

#define UPDATE_COUNT 2
#define EMB_CAPACITY (200000 * 64)

// Combined table in fp16: emb[e*64+d] = (half)(hw[widx[0,e,d]] + hw[widx[1,e,d]])
__device__ __half g_emb_h[EMB_CAPACITY];

// ---------------------------------------------------------------------------
// Kernel 1: build combined table. At the L1tex wavefront floor. widx .cs
// (streaming; keep hot hw resident in L2), hw .cg (skip L1).
// ---------------------------------------------------------------------------
__global__ void __launch_bounds__(256) build_emb_kernel(
    const int4* __restrict__ widx,
    const float* __restrict__ hw,
    int n8,                       // emb_elems / 8
    int stride4)                  // emb_elems / 4 (u-stride in int4 units)
{
    int i = blockIdx.x * blockDim.x + threadIdx.x;
    if (i >= n8) return;

    int4 a0 = __ldcs(&widx[2 * i]);
    int4 a1 = __ldcs(&widx[2 * i + 1]);
    int4 b0 = __ldcs(&widx[2 * i + stride4]);
    int4 b1 = __ldcs(&widx[2 * i + 1 + stride4]);

    float f0 = __ldcg(&hw[a0.x]) + __ldcg(&hw[b0.x]);
    float f1 = __ldcg(&hw[a0.y]) + __ldcg(&hw[b0.y]);
    float f2 = __ldcg(&hw[a0.z]) + __ldcg(&hw[b0.z]);
    float f3 = __ldcg(&hw[a0.w]) + __ldcg(&hw[b0.w]);
    float f4 = __ldcg(&hw[a1.x]) + __ldcg(&hw[b1.x]);
    float f5 = __ldcg(&hw[a1.y]) + __ldcg(&hw[b1.y]);
    float f6 = __ldcg(&hw[a1.z]) + __ldcg(&hw[b1.z]);
    float f7 = __ldcg(&hw[a1.w]) + __ldcg(&hw[b1.w]);

    __half2 h0 = __floats2half2_rn(f0, f1);
    __half2 h1 = __floats2half2_rn(f2, f3);
    __half2 h2 = __floats2half2_rn(f4, f5);
    __half2 h3 = __floats2half2_rn(f6, f7);

    uint4 o;
    o.x = *reinterpret_cast<uint32_t*>(&h0);
    o.y = *reinterpret_cast<uint32_t*>(&h1);
    o.z = *reinterpret_cast<uint32_t*>(&h2);
    o.w = *reinterpret_cast<uint32_t*>(&h3);
    reinterpret_cast<uint4*>(g_emb_h)[i] = o;
}

// ---------------------------------------------------------------------------
// Kernel 2: embedding bag. Warp-per-bag; fp16 rows are 128B -> one warp
// LDG.128 covers FOUR token rows (lane groups of 8). 8-token loop = MLP 2
// per lane. HADD2 accumulation (chain ~13, |partial|<0.06, fp16-safe).
// fp32 fold across the 4 token groups + 256B coalesced store.
// ---------------------------------------------------------------------------
__global__ void __launch_bounds__(256) bag_sum_kernel(
    const int* __restrict__ x,
    const int* __restrict__ offsets,
    float* __restrict__ out,
    int num_bags, int total)
{
    const int BPB = 8;                      // bags (warps) per block
    __shared__ int sh[BPB][64];

    int w    = threadIdx.x >> 5;
    int lane = threadIdx.x & 31;
    int bag  = blockIdx.x * BPB + w;
    if (bag >= num_bags) return;

    int start = __ldg(&offsets[bag]);
    int end   = (bag + 1 < num_bags) ? __ldg(&offsets[bag + 1]) : total;
    int len   = end - start;

    for (int t = lane; t < len; t += 32)
        sh[w][t] = __ldg(&x[start + t]);
    __syncwarp();

    const uint4* __restrict__ emb16 = reinterpret_cast<const uint4*>(g_emb_h);
    int g = lane >> 3;                      // token group 0..3
    int q = lane & 7;                       // 16B chunk within 128B row

    __half2 acc0 = __float2half2_rn(0.f);
    __half2 acc1 = acc0, acc2 = acc0, acc3 = acc0;

    int t = 0;
    // 8 tokens per iteration: 2 independent LDG.128 in flight per lane
    for (; t + 8 <= len; t += 8) {
        uint4 va = __ldg(&emb16[(unsigned)sh[w][t + 0 + g] * 8 + q]);
        uint4 vb = __ldg(&emb16[(unsigned)sh[w][t + 4 + g] * 8 + q]);
        acc0 = __hadd2(acc0, *reinterpret_cast<const __half2*>(&va.x));
        acc1 = __hadd2(acc1, *reinterpret_cast<const __half2*>(&va.y));
        acc2 = __hadd2(acc2, *reinterpret_cast<const __half2*>(&va.z));
        acc3 = __hadd2(acc3, *reinterpret_cast<const __half2*>(&va.w));
        acc0 = __hadd2(acc0, *reinterpret_cast<const __half2*>(&vb.x));
        acc1 = __hadd2(acc1, *reinterpret_cast<const __half2*>(&vb.y));
        acc2 = __hadd2(acc2, *reinterpret_cast<const __half2*>(&vb.z));
        acc3 = __hadd2(acc3, *reinterpret_cast<const __half2*>(&vb.w));
    }
    for (; t + 4 <= len; t += 4) {
        uint4 v = __ldg(&emb16[(unsigned)sh[w][t + g] * 8 + q]);
        acc0 = __hadd2(acc0, *reinterpret_cast<const __half2*>(&v.x));
        acc1 = __hadd2(acc1, *reinterpret_cast<const __half2*>(&v.y));
        acc2 = __hadd2(acc2, *reinterpret_cast<const __half2*>(&v.z));
        acc3 = __hadd2(acc3, *reinterpret_cast<const __half2*>(&v.w));
    }
    if (t + g < len) {                      // tail: 1-3 tokens
        uint4 v = __ldg(&emb16[(unsigned)sh[w][t + g] * 8 + q]);
        acc0 = __hadd2(acc0, *reinterpret_cast<const __half2*>(&v.x));
        acc1 = __hadd2(acc1, *reinterpret_cast<const __half2*>(&v.y));
        acc2 = __hadd2(acc2, *reinterpret_cast<const __half2*>(&v.z));
        acc3 = __hadd2(acc3, *reinterpret_cast<const __half2*>(&v.w));
    }

    // Convert to fp32, then fold the 4 token groups
    float2 a0 = __half22float2(acc0);
    float2 a1 = __half22float2(acc1);
    float2 a2 = __half22float2(acc2);
    float2 a3 = __half22float2(acc3);

    #pragma unroll
    for (int off = 16; off >= 8; off >>= 1) {
        a0.x += __shfl_xor_sync(0xffffffffu, a0.x, off);
        a0.y += __shfl_xor_sync(0xffffffffu, a0.y, off);
        a1.x += __shfl_xor_sync(0xffffffffu, a1.x, off);
        a1.y += __shfl_xor_sync(0xffffffffu, a1.y, off);
        a2.x += __shfl_xor_sync(0xffffffffu, a2.x, off);
        a2.y += __shfl_xor_sync(0xffffffffu, a2.y, off);
        a3.x += __shfl_xor_sync(0xffffffffu, a3.x, off);
        a3.y += __shfl_xor_sync(0xffffffffu, a3.y, off);
    }

    if (lane < 8) {                         // 8 lanes x 32B = 256B coalesced
        float4 lo = make_float4(a0.x, a0.y, a1.x, a1.y);
        float4 hi = make_float4(a2.x, a2.y, a3.x, a3.y);
        float4* o = reinterpret_cast<float4*>(out) + (unsigned)bag * 16 + q * 2;
        o[0] = lo;
        o[1] = hi;
    }
}

// ---------------------------------------------------------------------------
extern "C" void kernel_launch(void* const* d_in, const int* in_sizes, int n_in,
                              void* d_out, int out_size)
{
    const int*   x       = (const int*)  d_in[0];
    const int*   offsets = (const int*)  d_in[1];
    const float* hw      = (const float*)d_in[2];
    const int*   widx    = (const int*)  d_in[3];

    int total     = in_sizes[0];
    int num_bags  = in_sizes[1];
    int wid_sz    = in_sizes[3];
    int emb_elems = wid_sz / UPDATE_COUNT;

    int n8 = emb_elems / 8;
    int threads1 = 256;
    int blocks1  = (n8 + threads1 - 1) / threads1;
    build_emb_kernel<<<blocks1, threads1>>>(
        (const int4*)widx, hw, n8, emb_elems / 4);

    int blocks2 = (num_bags + 7) / 8;
    bag_sum_kernel<<<blocks2, 256>>>(x, offsets, (float*)d_out, num_bags, total);
}